// round 10
// baseline (speedup 1.0000x reference)
#include <cuda_runtime.h>
#include <math_constants.h>

// x[B=4, C=256, H=200, W=320] f32 -> out[B,H,W] f32
#define Bn 4
#define Cn 256
#define Hn 200
#define Wn 320
#define HWn (Hn * Wn)        // 64000
#define HW4 (HWn / 4)        // 16000 float4/plane
#define NPIX (Bn * HWn)      // 256000
#define GW (Wn / 4)          // 80 groups/row
#define LANES 96             // 3 warps cover GW (16 idle lanes)

#define NEG_INF (-CUDART_INF_F)

__device__ float4 g_pD[4 * Bn * HW4];   // 4 MB: per-chunk partial depth max
__device__ float  g_D[NPIX];            // 1 MB: depthwise max

__device__ __forceinline__ float4 f4max(float4 a, float4 b) {
    return make_float4(fmaxf(a.x, b.x), fmaxf(a.y, b.y),
                       fmaxf(a.z, b.z), fmaxf(a.w, b.w));
}

// ---- K1a: partial depthwise max over 64-channel chunk (pure fmax) ----------
__global__ void __launch_bounds__(256)
dmax_partial_kernel(const float* __restrict__ x) {
    const int g = blockIdx.x * 256 + threadIdx.x;   // 0..Bn*HW4-1 exact
    const int chunk = blockIdx.y;                   // 0..3
    const int b  = g / HW4;
    const int pg = g - b * HW4;

    const float4* __restrict__ src = reinterpret_cast<const float4*>(x)
        + (size_t)(b * Cn + chunk * 64) * HW4 + pg;

    float4 a0 = make_float4(NEG_INF, NEG_INF, NEG_INF, NEG_INF);
    float4 a1 = a0, a2 = a0, a3 = a0;
#pragma unroll 4
    for (int c = 0; c < 64; c += 16) {
        float4 v[16];
#pragma unroll
        for (int j = 0; j < 16; ++j) v[j] = __ldg(src + (size_t)(c + j) * HW4);
#pragma unroll
        for (int j = 0; j < 16; j += 4) {
            a0 = f4max(a0, v[j + 0]);
            a1 = f4max(a1, v[j + 1]);
            a2 = f4max(a2, v[j + 2]);
            a3 = f4max(a3, v[j + 3]);
        }
    }
    g_pD[(size_t)chunk * (Bn * HW4) + g] = f4max(f4max(a0, a1), f4max(a2, a3));
}

// ---- K1b: merge 4 partials -> g_D; zero the output ------------------------
__global__ void __launch_bounds__(256)
dmax_merge_kernel(float* __restrict__ out) {
    const int g = blockIdx.x * 256 + threadIdx.x;   // 0..Bn*HW4-1 exact
    float4 m = f4max(f4max(g_pD[g], g_pD[Bn * HW4 + g]),
                     f4max(g_pD[2 * Bn * HW4 + g], g_pD[3 * Bn * HW4 + g]));
    reinterpret_cast<float4*>(g_D)[g] = m;
    reinterpret_cast<float4*>(out)[g] = make_float4(0.f, 0.f, 0.f, 0.f);
}

// ---- K2: per-(b,c) dense separable 9x9 windowmax sweep + lazy D + emit -----
// Block = one (b, c) plane; 96 threads = 3 warps covering 80 float4 groups.
// Each thread sweeps all rows (no vertical re-read); horizontal halo via shfl,
// warp-edge lanes fetch one halo float4 from gmem. D is checked LAZILY only
// when the local-max test passes (~1/81 of elements), removing 16M LDGs.
__global__ void __launch_bounds__(LANES)
sweep_kernel(const float* __restrict__ x, float* __restrict__ out) {
    const int gx   = threadIdx.x;          // float4 group 0..95 (80..95 idle)
    const int lane = threadIdx.x & 31;
    const int c = blockIdx.x & (Cn - 1);
    const int b = blockIdx.x >> 8;

    const float4* __restrict__ plane4 =
        reinterpret_cast<const float4*>(x) + (size_t)(b * Cn + c) * HW4;

    const bool active = gx < GW;
    const bool lhalo = (lane == 0)  && (gx != 0) && active;  // gx 32, 64
    const bool rhalo = (lane == 31) && (gx < GW - 1);        // gx 31, 63

    const float4 NEG4 = make_float4(NEG_INF, NEG_INF, NEG_INF, NEG_INF);
    float4 vr[8], hmr[2], pr[4], qd[8], oc[2];
#pragma unroll
    for (int i = 0; i < 8; ++i) { vr[i] = NEG4; qd[i] = NEG4; }
    hmr[0] = hmr[1] = NEG4; oc[0] = oc[1] = NEG4;
    pr[0] = pr[1] = pr[2] = pr[3] = NEG4;

    for (int it = 0; it < 26; ++it) {
#pragma unroll
        for (int u = 0; u < 8; ++u) {
            const int r = it * 8 + u - 4;
            const int ly = min(max(r, 0), Hn - 1);   // clamp dup: max-safe
            const float4* rowp = plane4 + ly * GW;

            const float4 va = active ? __ldg(rowp + gx) : NEG4;
            const float4 hl = lhalo ? __ldg(rowp + gx - 1) : NEG4;
            const float4 hr = rhalo ? __ldg(rowp + gx + 1) : NEG4;
            vr[u & 7] = va;

            // prefix p0..p3 / suffix s0..s3 of own 4 cols (s0 == p3)
            const float p1 = fmaxf(va.x, va.y);
            const float p2 = fmaxf(p1, va.z);
            const float p3 = fmaxf(p2, va.w);
            const float s2 = fmaxf(va.z, va.w);
            const float s1 = fmaxf(va.y, s2);

            // neighbor arrays via shfl
            float ls0 = __shfl_up_sync(0xFFFFFFFFu, p3, 1);
            float ls1 = __shfl_up_sync(0xFFFFFFFFu, s1, 1);
            float ls2 = __shfl_up_sync(0xFFFFFFFFu, s2, 1);
            float ls3 = __shfl_up_sync(0xFFFFFFFFu, va.w, 1);
            float rp0 = __shfl_down_sync(0xFFFFFFFFu, va.x, 1);
            float rp1 = __shfl_down_sync(0xFFFFFFFFu, p1, 1);
            float rp2 = __shfl_down_sync(0xFFFFFFFFu, p2, 1);
            float rp3 = __shfl_down_sync(0xFFFFFFFFu, p3, 1);

            // warp-edge fixups from gmem halos (hl/hr = -inf when absent)
            const float hs3 = hl.w;
            const float hs2 = fmaxf(hl.z, hs3);
            const float hs1 = fmaxf(hl.y, hs2);
            const float hs0 = fmaxf(hl.x, hs1);
            ls0 = (lane == 0) ? hs0 : ls0;
            ls1 = (lane == 0) ? hs1 : ls1;
            ls2 = (lane == 0) ? hs2 : ls2;
            ls3 = (lane == 0) ? hs3 : ls3;
            const float hp0 = hr.x;
            const float hp1 = fmaxf(hp0, hr.y);
            const float hp2 = fmaxf(hp1, hr.z);
            const float hp3 = fmaxf(hp2, hr.w);
            rp0 = (lane == 31) ? hp0 : rp0;
            rp1 = (lane == 31) ? hp1 : rp1;
            rp2 = (lane == 31) ? hp2 : rp2;
            rp3 = (lane == 31) ? hp3 : rp3;

            // horizontal 9-max
            float4 hm;
            hm.x = fmaxf(fmaxf(ls0, rp0), p3);
            hm.y = fmaxf(fmaxf(ls1, rp1), p3);
            hm.z = fmaxf(fmaxf(ls2, rp2), p3);
            hm.w = fmaxf(fmaxf(ls3, rp3), p3);

            // vertical sliding 9-max: pair/quad/oct chain, 4 f4max per row
            const float4 hprev = hmr[(u + 1) & 1];
            hmr[u & 1] = hm;
            pr[u & 3] = f4max(hm, hprev);                   // rows {r-1, r}
            qd[u & 7] = f4max(pr[u & 3], pr[(u + 2) & 3]);  // {r-3..r}
            oc[u & 1] = f4max(qd[u & 7], qd[(u + 4) & 7]);  // {r-7..r}

            if (it > 0 && active) {
                const float4 win = f4max(oc[u & 1], oc[(u + 1) & 1]); // {r-8..r}
                const int j = r - 4;                        // center row
                const float4 vc = vr[(u + 4) & 7];          // x at row j
                // Lazy D check: only on local-max pass (~1/81 of elements).
                // win >= vc always (window includes center), so pass <=> ==.
                const int pbase = b * HWn + j * Wn + gx * 4;
                if (win.x <= vc.x) {
                    if (vc.x == g_D[pbase + 0]) atomicAdd(out + pbase + 0, vc.x);
                }
                if (win.y <= vc.y) {
                    if (vc.y == g_D[pbase + 1]) atomicAdd(out + pbase + 1, vc.y);
                }
                if (win.z <= vc.z) {
                    if (vc.z == g_D[pbase + 2]) atomicAdd(out + pbase + 2, vc.z);
                }
                if (win.w <= vc.w) {
                    if (vc.w == g_D[pbase + 3]) atomicAdd(out + pbase + 3, vc.w);
                }
            }
        }
    }
}

extern "C" void kernel_launch(void* const* d_in, const int* in_sizes, int n_in,
                              void* d_out, int out_size) {
    const float* x = (const float*)d_in[0];
    float* out = (float*)d_out;
    (void)in_sizes; (void)n_in; (void)out_size;

    dim3 gA((Bn * HW4) / 256, 4);
    dmax_partial_kernel<<<gA, 256>>>(x);               // 250x4 blocks
    dmax_merge_kernel<<<(Bn * HW4) / 256, 256>>>(out); // 250 blocks
    sweep_kernel<<<Bn * Cn, LANES>>>(x, out);          // 1024 blocks
}

// round 11
// speedup vs baseline: 1.4051x; 1.4051x over previous
#include <cuda_runtime.h>
#include <math_constants.h>

// x[B=4, C=256, H=200, W=320] f32 -> out[B,H,W] f32
#define Bn 4
#define Cn 256
#define Hn 200
#define Wn 320
#define HWn (Hn * Wn)        // 64000
#define HW4 (HWn / 4)        // 16000 float4/plane
#define NPIX (Bn * HWn)      // 256000
#define GW (Wn / 4)          // 80 groups/row
#define LANES 96

#define NEG_INF (-CUDART_INF_F)

__device__ float4 g_pD[4 * Bn * HW4];   // 4 MB: per-chunk partial depth max
__device__ float  g_D[NPIX];            // 1 MB: depthwise max

__device__ __forceinline__ float4 f4max(float4 a, float4 b) {
    return make_float4(fmaxf(a.x, b.x), fmaxf(a.y, b.y),
                       fmaxf(a.z, b.z), fmaxf(a.w, b.w));
}

// ---- K1a: partial depthwise max over 64-channel chunk (pure fmax) ----------
__global__ void __launch_bounds__(256)
dmax_partial_kernel(const float* __restrict__ x) {
    const int g = blockIdx.x * 256 + threadIdx.x;   // 0..Bn*HW4-1 exact
    const int chunk = blockIdx.y;                   // 0..3
    const int b  = g / HW4;
    const int pg = g - b * HW4;

    const float4* __restrict__ src = reinterpret_cast<const float4*>(x)
        + (size_t)(b * Cn + chunk * 64) * HW4 + pg;

    float4 a0 = make_float4(NEG_INF, NEG_INF, NEG_INF, NEG_INF);
    float4 a1 = a0, a2 = a0, a3 = a0;
#pragma unroll 4
    for (int c = 0; c < 64; c += 16) {
        float4 v[16];
#pragma unroll
        for (int j = 0; j < 16; ++j) v[j] = __ldg(src + (size_t)(c + j) * HW4);
#pragma unroll
        for (int j = 0; j < 16; j += 4) {
            a0 = f4max(a0, v[j + 0]);
            a1 = f4max(a1, v[j + 1]);
            a2 = f4max(a2, v[j + 2]);
            a3 = f4max(a3, v[j + 3]);
        }
    }
    g_pD[(size_t)chunk * (Bn * HW4) + g] = f4max(f4max(a0, a1), f4max(a2, a3));
}

// ---- K1b: merge 4 partials -> g_D; zero the output ------------------------
__global__ void __launch_bounds__(256)
dmax_merge_kernel(float* __restrict__ out) {
    const int g = blockIdx.x * 256 + threadIdx.x;   // 0..Bn*HW4-1 exact
    float4 m = f4max(f4max(g_pD[g], g_pD[Bn * HW4 + g]),
                     f4max(g_pD[2 * Bn * HW4 + g], g_pD[3 * Bn * HW4 + g]));
    reinterpret_cast<float4*>(g_D)[g] = m;
    reinterpret_cast<float4*>(out)[g] = make_float4(0.f, 0.f, 0.f, 0.f);
}

// ---- K2: per-(b,c) dense separable 9x9 windowmax, smem halos, prefetch -----
// Block = one (b,c) plane. 96 threads (80 active float4 columns). A padded
// 8-row smem ring provides: horizontal halos (no shfl, no edge branches),
// and the center row vc (4 iterations back). D rows prefetched 1 iter ahead.
__global__ void __launch_bounds__(LANES)
sweep_kernel(const float* __restrict__ x, float* __restrict__ out) {
    __shared__ float srow[8][336];   // cols: [0..3] pad, [4..323] data, [324..327] pad

    const int tid = threadIdx.x;
    const int gx  = tid;
    const bool active = gx < GW;
    const int c = blockIdx.x & (Cn - 1);
    const int b = blockIdx.x >> 8;

    // -inf pads, written once
    if (tid < 64) {
        const int r = tid >> 3, k = tid & 7;
        srow[r][(k < 4) ? k : (320 + k)] = NEG_INF;
    }
    __syncthreads();

    const float4* __restrict__ plane4 =
        reinterpret_cast<const float4*>(x) + (size_t)(b * Cn + c) * HW4;
    const float4* __restrict__ D4 =
        reinterpret_cast<const float4*>(g_D) + (size_t)b * HW4;

    const float4 NEG4 = make_float4(NEG_INF, NEG_INF, NEG_INF, NEG_INF);
    float4 hmr[8], m2r[4], m4r[8];
#pragma unroll
    for (int i = 0; i < 8; ++i) { hmr[i] = NEG4; m4r[i] = NEG4; }
    m2r[0] = m2r[1] = m2r[2] = m2r[3] = NEG4;

    // prefetch registers
    float4 va_cur = active ? __ldg(plane4 + 0 * GW + gx) : NEG4;  // row clamp(-4)=0
    float4 dv_cur = NEG4;

    for (int it = 0; it < 26; ++it) {
#pragma unroll
        for (int u = 0; u < 8; ++u) {
            const int i = it * 8 + u;          // iteration index; plane row r=i-4

            const float4 va = va_cur;
            const float4 dv = dv_cur;

            // ---- prefetch next row of x (row clamp(i+1-4)) ----
            {
                int lyn = i - 3;
                lyn = lyn < 0 ? 0 : (lyn > Hn - 1 ? Hn - 1 : lyn);
                va_cur = active ? __ldg(plane4 + lyn * GW + gx) : NEG4;
            }

            // vc = x at center row j = i-8 (stored 4 iterations ago)
            const float4 vc = active ?
                *reinterpret_cast<const float4*>(&srow[(u + 4) & 7][4 + 4 * gx]) : NEG4;

            // store current row, then exchange halos via smem
            if (active)
                *reinterpret_cast<float4*>(&srow[u & 7][4 + 4 * gx]) = va;
            __syncthreads();
            const float4 hl = active ?
                *reinterpret_cast<const float4*>(&srow[u & 7][4 * gx]) : NEG4;
            const float4 hr = active ?
                *reinterpret_cast<const float4*>(&srow[u & 7][4 * gx + 8]) : NEG4;

            // ---- horizontal 9-max for 4 columns ----
            const float p3  = fmaxf(fmaxf(va.x, va.y), fmaxf(va.z, va.w));
            const float hs3 = hl.w;
            const float hs2 = fmaxf(hl.z, hs3);
            const float hs1 = fmaxf(hl.y, hs2);
            const float hs0 = fmaxf(hl.x, hs1);
            const float hp0 = hr.x;
            const float hp1 = fmaxf(hp0, hr.y);
            const float hp2 = fmaxf(hp1, hr.z);
            const float hp3 = fmaxf(hp2, hr.w);
            float4 hm;
            hm.x = fmaxf(hs0, fmaxf(p3, hp0));
            hm.y = fmaxf(hs1, fmaxf(p3, hp1));
            hm.z = fmaxf(hs2, fmaxf(p3, hp2));
            hm.w = fmaxf(hs3, fmaxf(p3, hp3));

            // ---- vertical sliding 9-max via pair/quad/oct rings ----
            const float4 hm8 = hmr[u & 7];            // hm(i-8), read before store
            const float4 m2  = f4max(hm, hmr[(u + 7) & 7]);   // rows {i-1, i}
            hmr[u & 7] = hm;
            const float4 m4  = f4max(m2, m2r[(u + 2) & 3]);   // {i-3..i}
            m2r[u & 3] = m2;
            const float4 m8  = f4max(m4, m4r[(u + 4) & 7]);   // {i-7..i}
            m4r[u & 7] = m4;
            const float4 win = f4max(m8, hm8);                // {i-8..i}

            // ---- emit for center row j = i-8 ----
            if (it > 0 && active) {
                const int j = i - 8;
                const int pbase = b * HWn + j * Wn + gx * 4;
                // win >= vc always (window includes center): pass <=> win == vc
                if (vc.x == dv.x && win.x <= vc.x) atomicAdd(out + pbase + 0, vc.x);
                if (vc.y == dv.y && win.y <= vc.y) atomicAdd(out + pbase + 1, vc.y);
                if (vc.z == dv.z && win.z <= vc.z) atomicAdd(out + pbase + 2, vc.z);
                if (vc.w == dv.w && win.w <= vc.w) atomicAdd(out + pbase + 3, vc.w);
            }

            // ---- prefetch D row for next iteration (j+1 = i-7) ----
            if (active && i >= 7 && i <= 206)
                dv_cur = __ldg(D4 + (i - 7) * GW + gx);
        }
    }
}

extern "C" void kernel_launch(void* const* d_in, const int* in_sizes, int n_in,
                              void* d_out, int out_size) {
    const float* x = (const float*)d_in[0];
    float* out = (float*)d_out;
    (void)in_sizes; (void)n_in; (void)out_size;

    dim3 gA((Bn * HW4) / 256, 4);
    dmax_partial_kernel<<<gA, 256>>>(x);               // 250x4 blocks
    dmax_merge_kernel<<<(Bn * HW4) / 256, 256>>>(out); // 250 blocks
    sweep_kernel<<<Bn * Cn, LANES>>>(x, out);          // 1024 blocks
}

// round 12
// speedup vs baseline: 1.9673x; 1.4001x over previous
#include <cuda_runtime.h>
#include <math_constants.h>

// x[B=4, C=256, H=200, W=320] f32 -> out[B,H,W] f32
#define Bn 4
#define Cn 256
#define Hn 200
#define Wn 320
#define HWn (Hn * Wn)        // 64000
#define HW4 (HWn / 4)        // 16000 float4/plane
#define NPIX (Bn * HWn)      // 256000
#define GW (Wn / 4)          // 80 groups/row

#define NEG_INF (-CUDART_INF_F)

__device__ float4 g_pD[4 * Bn * HW4];   // 4 MB: per-chunk partial depth max
__device__ float  g_D[NPIX];            // 1 MB: depthwise max

__device__ __forceinline__ float4 f4max(float4 a, float4 b) {
    return make_float4(fmaxf(a.x, b.x), fmaxf(a.y, b.y),
                       fmaxf(a.z, b.z), fmaxf(a.w, b.w));
}

// ---- K1a: partial depthwise max over 64-channel chunk (pure fmax) ----------
__global__ void __launch_bounds__(256)
dmax_partial_kernel(const float* __restrict__ x) {
    const int g = blockIdx.x * 256 + threadIdx.x;   // 0..Bn*HW4-1 exact
    const int chunk = blockIdx.y;                   // 0..3
    const int b  = g / HW4;
    const int pg = g - b * HW4;

    const float4* __restrict__ src = reinterpret_cast<const float4*>(x)
        + (size_t)(b * Cn + chunk * 64) * HW4 + pg;

    float4 a0 = make_float4(NEG_INF, NEG_INF, NEG_INF, NEG_INF);
    float4 a1 = a0, a2 = a0, a3 = a0;
#pragma unroll 4
    for (int c = 0; c < 64; c += 16) {
        float4 v[16];
#pragma unroll
        for (int j = 0; j < 16; ++j) v[j] = __ldg(src + (size_t)(c + j) * HW4);
#pragma unroll
        for (int j = 0; j < 16; j += 4) {
            a0 = f4max(a0, v[j + 0]);
            a1 = f4max(a1, v[j + 1]);
            a2 = f4max(a2, v[j + 2]);
            a3 = f4max(a3, v[j + 3]);
        }
    }
    g_pD[(size_t)chunk * (Bn * HW4) + g] = f4max(f4max(a0, a1), f4max(a2, a3));
}

// ---- K1b: merge 4 partials -> g_D; zero the output ------------------------
__global__ void __launch_bounds__(256)
dmax_merge_kernel(float* __restrict__ out) {
    const int g = blockIdx.x * 256 + threadIdx.x;   // 0..Bn*HW4-1 exact
    float4 m = f4max(f4max(g_pD[g], g_pD[Bn * HW4 + g]),
                     f4max(g_pD[2 * Bn * HW4 + g], g_pD[3 * Bn * HW4 + g]));
    reinterpret_cast<float4*>(g_D)[g] = m;
    reinterpret_cast<float4*>(out)[g] = make_float4(0.f, 0.f, 0.f, 0.f);
}

// ---- K2: per-(b,c) dense separable 9x9 windowmax, batch-8 MLP, shfl halos --
// Block = one (b,c) plane. 128 threads = 4 warps; warp w: lanes 0..19 own
// output groups 20w..20w+19, lane 20 loads left-halo group 20w-1, lane 21
// loads right-halo group 20w+20. All halo exchange is in-warp shfl.idx.
// Each batch issues its 8 row LDGs + 8 D LDGs up front (MLP ~16/thread-group).
__global__ void __launch_bounds__(128)
sweep_kernel(const float* __restrict__ x, float* __restrict__ out) {
    const int tid  = threadIdx.x;
    const int wid  = tid >> 5;
    const int lane = tid & 31;
    const int c = blockIdx.x & (Cn - 1);
    const int b = blockIdx.x >> 8;

    const bool outlane = lane < 20;
    int ldgx;                                 // which group this lane loads
    if (lane < 20)       ldgx = wid * 20 + lane;
    else if (lane == 20) ldgx = wid * 20 - 1;        // left halo (w=0 -> -1)
    else if (lane == 21) ldgx = wid * 20 + 20;       // right halo (w=3 -> 80)
    else                 ldgx = -1;
    const bool ldvalid = (ldgx >= 0) && (ldgx < GW);
    const int gx = wid * 20 + lane;                   // output group (lanes<20)
    const int srcL = (lane == 0)  ? 20 : lane - 1;
    const int srcR = (lane == 19) ? 21 : lane + 1;

    const float4* __restrict__ plane4 =
        reinterpret_cast<const float4*>(x) + (size_t)(b * Cn + c) * HW4;
    const float4* __restrict__ D4 =
        reinterpret_cast<const float4*>(g_D) + (size_t)b * HW4;

    const float4 NEG4 = make_float4(NEG_INF, NEG_INF, NEG_INF, NEG_INF);
    float4 hmr[8], m2r[2], m4r[4], vprev[4];
#pragma unroll
    for (int i = 0; i < 8; ++i) hmr[i] = NEG4;
    m2r[0] = m2r[1] = NEG4;
    m4r[0] = m4r[1] = m4r[2] = m4r[3] = NEG4;
    vprev[0] = vprev[1] = vprev[2] = vprev[3] = NEG4;

    for (int it = 0; it < 26; ++it) {
        // ---- front-batched loads: 8 x rows + 8 D rows (independent) ----
        float4 va[8], dv[8];
#pragma unroll
        for (int u = 0; u < 8; ++u) {
            int ly = 8 * it + u - 4;
            ly = ly < 0 ? 0 : (ly > Hn - 1 ? Hn - 1 : ly);   // clamp: max-safe
            va[u] = ldvalid ? __ldg(plane4 + ly * GW + ldgx) : NEG4;
        }
#pragma unroll
        for (int u = 0; u < 8; ++u) {
            const int j = 8 * (it - 1) + u;        // center row this batch
            dv[u] = (it > 0 && outlane) ? __ldg(D4 + j * GW + gx) : NEG4;
        }

#pragma unroll
        for (int u = 0; u < 8; ++u) {
            const float4 v = va[u];
            // own prefixes/suffixes
            const float p1 = fmaxf(v.x, v.y);
            const float p2 = fmaxf(p1, v.z);
            const float p3 = fmaxf(p2, v.w);
            const float s3 = v.w;
            const float s2 = fmaxf(v.z, s3);
            const float s1 = fmaxf(v.y, s2);
            // halo exchange (uniform shfl.idx, full warp)
            const float ls0 = __shfl_sync(0xFFFFFFFFu, p3,  srcL);
            const float ls1 = __shfl_sync(0xFFFFFFFFu, s1,  srcL);
            const float ls2 = __shfl_sync(0xFFFFFFFFu, s2,  srcL);
            const float ls3 = __shfl_sync(0xFFFFFFFFu, s3,  srcL);
            const float rp0 = __shfl_sync(0xFFFFFFFFu, v.x, srcR);
            const float rp1 = __shfl_sync(0xFFFFFFFFu, p1,  srcR);
            const float rp2 = __shfl_sync(0xFFFFFFFFu, p2,  srcR);
            const float rp3 = __shfl_sync(0xFFFFFFFFu, p3,  srcR);
            // horizontal 9-max
            float4 hm;
            hm.x = fmaxf(ls0, fmaxf(p3, rp0));
            hm.y = fmaxf(ls1, fmaxf(p3, rp1));
            hm.z = fmaxf(ls2, fmaxf(p3, rp2));
            hm.w = fmaxf(ls3, fmaxf(p3, rp3));

            // vertical 9-max (non-recursive rings, read-before-write)
            const float4 hm8 = hmr[u];                       // hm(i-8)
            const float4 m2  = f4max(hm, hmr[(u + 7) & 7]);  // {i-1, i}
            const float4 m4  = f4max(m2, m2r[u & 1]);        // {i-3..i}
            const float4 m8  = f4max(m4, m4r[u & 3]);        // {i-7..i}
            hmr[u]     = hm;
            m2r[u & 1] = m2;
            m4r[u & 3] = m4;
            const float4 win = f4max(m8, hm8);               // rows j-4..j+4

            // emit for center row j = 8(it-1)+u
            if (it > 0 && outlane) {
                const float4 vc  = (u < 4) ? vprev[u] : va[u - 4];
                const float4 dvv = dv[u];
                const int j = 8 * (it - 1) + u;
                const int pbase = b * HWn + j * Wn + gx * 4;
                // win >= vc always (window includes center): pass <=> ==
                if (vc.x == dvv.x && win.x <= vc.x) atomicAdd(out + pbase + 0, vc.x);
                if (vc.y == dvv.y && win.y <= vc.y) atomicAdd(out + pbase + 1, vc.y);
                if (vc.z == dvv.z && win.z <= vc.z) atomicAdd(out + pbase + 2, vc.z);
                if (vc.w == dvv.w && win.w <= vc.w) atomicAdd(out + pbase + 3, vc.w);
            }
        }
        vprev[0] = va[4]; vprev[1] = va[5]; vprev[2] = va[6]; vprev[3] = va[7];
    }
}

extern "C" void kernel_launch(void* const* d_in, const int* in_sizes, int n_in,
                              void* d_out, int out_size) {
    const float* x = (const float*)d_in[0];
    float* out = (float*)d_out;
    (void)in_sizes; (void)n_in; (void)out_size;

    dim3 gA((Bn * HW4) / 256, 4);
    dmax_partial_kernel<<<gA, 256>>>(x);               // 250x4 blocks
    dmax_merge_kernel<<<(Bn * HW4) / 256, 256>>>(out); // 250 blocks
    sweep_kernel<<<Bn * Cn, 128>>>(x, out);            // 1024 blocks
}